// round 16
// baseline (speedup 1.0000x reference)
#include <cuda_runtime.h>
#include <cuda_bf16.h>
#include <cstdint>

#define BN_  2
#define HH   64
#define WW   64
#define CC   128
#define HP   66
#define AREA 4356          // HP*HP
#define AREAP 4368         // padded stride (16B-aligned in bf16)
#define LL   4096          // HH*WW
#define NBLK 35            // ceil(AREA/128)

// ---------------- scratch ----------------
__device__ __nv_bfloat16 g_X2h[BN_ * AREA * CC + 128 * CC];   // x2 padded hi [b][a][c]
__device__ __nv_bfloat16 g_X2l[BN_ * AREA * CC + 128 * CC];   // x2 padded lo
__device__ __nv_bfloat16 g_XT2h[BN_ * CC * AREAP + 256];      // x2 padded hi, transposed, stride AREAP
__device__ __nv_bfloat16 g_XT2l[BN_ * CC * AREAP + 256];
__device__ float g_r  [BN_ * AREA];
__device__ float g_nm [BN_ * LL];
__device__ float g_D  [(size_t)BN_ * AREA * AREA + 128];
__device__ float g_S  [(size_t)BN_ * LL * LL];        // Sh (pooled-horizontal scores)
__device__ float g_A  [(size_t)BN_ * LL * LL];        // att
__device__ __nv_bfloat16 g_W2h[(size_t)BN_ * LL * LL];
__device__ __nv_bfloat16 g_W2l[(size_t)BN_ * LL * LL];
__device__ __nv_bfloat16 g_V1h[BN_ * LL * CC];
__device__ __nv_bfloat16 g_V1l[BN_ * LL * CC];

// ================= portable PTX helpers =================
__device__ __forceinline__ uint32_t smem_u32(const void* p) {
    uint32_t a;
    asm("{ .reg .u64 t; cvta.to.shared.u64 t, %1; cvt.u32.u64 %0, t; }" : "=r"(a) : "l"(p));
    return a;
}
#define CP_A16(dst, src) asm volatile("cp.async.cg.shared.global [%0], [%1], 16;" :: "r"(dst), "l"(src))
#define CP_COMMIT()      asm volatile("cp.async.commit_group;" ::: "memory")
#define CP_WAIT(n)       asm volatile("cp.async.wait_group %0;" :: "n"(n) : "memory")

#define LDM_X4(r0, r1, r2, r3, addr) \
    asm volatile("ldmatrix.sync.aligned.m8n8.x4.shared.b16 {%0,%1,%2,%3}, [%4];" \
        : "=r"(r0), "=r"(r1), "=r"(r2), "=r"(r3) : "r"(addr))
#define LDM_X4T(r0, r1, r2, r3, addr) \
    asm volatile("ldmatrix.sync.aligned.m8n8.x4.trans.shared.b16 {%0,%1,%2,%3}, [%4];" \
        : "=r"(r0), "=r"(r1), "=r"(r2), "=r"(r3) : "r"(addr))
#define MMA16816(d, a, b0v, b1v) \
    asm volatile("mma.sync.aligned.m16n8k16.row.col.f32.bf16.bf16.f32 " \
        "{%0,%1,%2,%3}, {%4,%5,%6,%7}, {%8,%9}, {%0,%1,%2,%3};" \
        : "+f"((d)[0]), "+f"((d)[1]), "+f"((d)[2]), "+f"((d)[3]) \
        : "r"((a)[0]), "r"((a)[1]), "r"((a)[2]), "r"((a)[3]), "r"(b0v), "r"(b1v))

// ---------------- transpose x2 → bf16 hi/lo both layouts (one x2 pass) ----------------
__global__ void k_xt2(const float* __restrict__ x2) {
    __shared__ float t[32][33];
    int b = blockIdx.z;
    int a0 = blockIdx.x * 32, c0 = blockIdx.y * 32;
    int tx = threadIdx.x, ty = threadIdx.y;
    #pragma unroll
    for (int i = 0; i < 4; i++) {
        int r = ty + i * 8;
        int a = a0 + r;
        if (a < AREA) {
            int ai = a / HP, aj = a % HP;
            float v = 0.f;
            if (ai >= 1 && ai <= HH && aj >= 1 && aj <= WW)
                v = x2[((size_t)(b * HH + ai - 1) * WW + aj - 1) * CC + c0 + tx];
            t[r][tx] = v;
            __nv_bfloat16 h = __float2bfloat16(v);
            size_t dst = ((size_t)(b * AREA + a)) * CC + c0 + tx;
            g_X2h[dst] = h;
            g_X2l[dst] = __float2bfloat16(v - __bfloat162float(h));
        }
    }
    __syncthreads();
    #pragma unroll
    for (int i = 0; i < 4; i++) {
        int r = ty + i * 8;
        if (a0 + tx < AREA) {
            float v = t[tx][r];
            __nv_bfloat16 h = __float2bfloat16(v);
            size_t dst = ((size_t)b * CC + c0 + r) * AREAP + a0 + tx;
            g_XT2h[dst] = h;
            g_XT2l[dst] = __float2bfloat16(v - __bfloat162float(h));
        }
    }
}

// ---------------- split x1 into bf16 hi/lo + zero output ----------------
__global__ void k_split(const float* __restrict__ x1, float* __restrict__ out) {
    int idx = blockIdx.x * blockDim.x + threadIdx.x;
    if (idx >= BN_ * LL * CC) return;
    float v = x1[idx];
    __nv_bfloat16 h = __float2bfloat16(v);
    g_V1h[idx] = h;
    g_V1l[idx] = __float2bfloat16(v - __bfloat162float(h));
    out[idx] = 0.f;
}

// ---------------- per-pixel squared norms ----------------
__global__ void k_rnorm(const float* __restrict__ x2) {
    int gw = (blockIdx.x * blockDim.x + threadIdx.x) >> 5;
    int lane = threadIdx.x & 31;
    if (gw >= BN_ * AREA) return;
    int a = gw % AREA, b = gw / AREA;
    int ai = a / HP, aj = a % HP;
    float s = 0.f;
    if (ai >= 1 && ai <= HH && aj >= 1 && aj <= WW) {
        const float4* p = (const float4*)(x2 + ((size_t)(b * HH + ai - 1) * WW + aj - 1) * CC);
        float4 v = p[lane];
        s = v.x * v.x + v.y * v.y + v.z * v.z + v.w * v.w;
        #pragma unroll
        for (int o = 16; o; o >>= 1) s += __shfl_xor_sync(0xffffffffu, s, o);
    }
    if (!lane) g_r[gw] = s;
}

// ---------------- patch norms ----------------
__global__ void k_nm() {
    int idx = blockIdx.x * blockDim.x + threadIdx.x;
    if (idx >= BN_ * LL) return;
    int l = idx & (LL - 1), b = idx / LL;
    int li = l >> 6, lj = l & 63;
    const float* rb = g_r + b * AREA;
    float s = 0.f;
    #pragma unroll
    for (int dy = 0; dy < 3; dy++)
        #pragma unroll
        for (int dx = 0; dx < 3; dx++)
            s += rb[(li + dy) * HP + lj + dx];
    g_nm[idx] = 1.f / fmaxf(sqrtf(s), 1e-4f);
}

// ---------------- D = X @ X^T via mma.sync bf16x3, symmetric blocks ----------------
#define DT_STR 136
#define DT_TILE (128 * DT_STR)
#define DT_SMEM (4 * DT_TILE * 2)       // 139264 B
__global__ __launch_bounds__(256, 1) void k_dgemm() {
    extern __shared__ __nv_bfloat16 sm[];
    int rem = blockIdx.x;
    int bm = 0;
    while (rem >= NBLK - bm) { rem -= NBLK - bm; bm++; }
    int bn = bm + rem;
    int b = blockIdx.z;
    int m0 = bm * 128, n0 = bn * 128;
    int tid = threadIdx.x, lane = tid & 31, wid = tid >> 5;
    int wm = wid >> 2, wn = wid & 3;

    const __nv_bfloat16* __restrict__ Axh = g_X2h + (size_t)b * AREA * CC;
    const __nv_bfloat16* __restrict__ Axl = g_X2l + (size_t)b * AREA * CC;
    const __nv_bfloat16* __restrict__ Bxh = g_XT2h + (size_t)b * CC * AREAP;
    const __nv_bfloat16* __restrict__ Bxl = g_XT2l + (size_t)b * CC * AREAP;
    float* __restrict__ Dp = g_D + (size_t)b * AREA * AREA;
    uint32_t sb = smem_u32(sm);

    #pragma unroll
    for (int q = 0; q < 8; q++) {
        int e = q * 256 + tid;
        int r = e >> 4, c = e & 15;
        uint32_t doff = (r * DT_STR + c * 8) * 2;
        size_t soA = (size_t)(m0 + r) * CC + c * 8;
        CP_A16(sb + 0 * DT_TILE * 2 + doff, Axh + soA);
        CP_A16(sb + 1 * DT_TILE * 2 + doff, Axl + soA);
        size_t soB = (size_t)r * AREAP + n0 + c * 8;
        CP_A16(sb + 2 * DT_TILE * 2 + doff, Bxh + soB);
        CP_A16(sb + 3 * DT_TILE * 2 + doff, Bxl + soB);
    }
    CP_COMMIT();
    CP_WAIT(0);
    __syncthreads();

    float acc[4][4][4];
    #pragma unroll
    for (int i = 0; i < 4; i++)
        #pragma unroll
        for (int j = 0; j < 4; j++)
            #pragma unroll
            for (int q = 0; q < 4; q++) acc[i][j][q] = 0.f;

    int frow = (lane & 7) + ((lane >> 3) & 1) * 8;
    int fcol = ((lane >> 4) & 1) * 8;

    #pragma unroll
    for (int ks = 0; ks < 8; ks++) {
        uint32_t ah[4][4], al[4][4], bh[2][4], bl[2][4];
        #pragma unroll
        for (int tm = 0; tm < 4; tm++) {
            uint32_t off = ((wm * 64 + tm * 16 + frow) * DT_STR + ks * 16 + fcol) * 2;
            LDM_X4(ah[tm][0], ah[tm][1], ah[tm][2], ah[tm][3], sb + 0 * DT_TILE * 2 + off);
            LDM_X4(al[tm][0], al[tm][1], al[tm][2], al[tm][3], sb + 1 * DT_TILE * 2 + off);
        }
        #pragma unroll
        for (int p = 0; p < 2; p++) {
            uint32_t off = ((ks * 16 + frow) * DT_STR + wn * 32 + p * 16 + fcol) * 2;
            LDM_X4T(bh[p][0], bh[p][1], bh[p][2], bh[p][3], sb + 2 * DT_TILE * 2 + off);
            LDM_X4T(bl[p][0], bl[p][1], bl[p][2], bl[p][3], sb + 3 * DT_TILE * 2 + off);
        }
        #pragma unroll
        for (int tm = 0; tm < 4; tm++) {
            #pragma unroll
            for (int tn = 0; tn < 4; tn++) {
                int p = tn >> 1, h2 = (tn & 1) * 2;
                MMA16816(acc[tm][tn], ah[tm], bh[p][h2], bh[p][h2 + 1]);
                MMA16816(acc[tm][tn], ah[tm], bl[p][h2], bl[p][h2 + 1]);
                MMA16816(acc[tm][tn], al[tm], bh[p][h2], bh[p][h2 + 1]);
            }
        }
    }

    #pragma unroll
    for (int tm = 0; tm < 4; tm++) {
        int row = m0 + wm * 64 + tm * 16 + (lane >> 2);
        #pragma unroll
        for (int tn = 0; tn < 4; tn++) {
            int col = n0 + wn * 32 + tn * 8 + (lane & 3) * 2;
            if (col < AREA) {
                if (row < AREA)
                    *(float2*)&Dp[(size_t)row * AREA + col] = make_float2(acc[tm][tn][0], acc[tm][tn][1]);
                if (row + 8 < AREA)
                    *(float2*)&Dp[(size_t)(row + 8) * AREA + col] = make_float2(acc[tm][tn][2], acc[tm][tn][3]);
            }
        }
    }

    if (bm == bn) return;

    __syncthreads();
    float* fs = (float*)sm;
    #pragma unroll
    for (int tm = 0; tm < 4; tm++) {
        int ml = wm * 64 + tm * 16 + (lane >> 2);
        #pragma unroll
        for (int tn = 0; tn < 4; tn++) {
            int nl = wn * 32 + tn * 8 + (lane & 3) * 2;
            fs[nl * 129 + ml]           = acc[tm][tn][0];
            fs[(nl + 1) * 129 + ml]     = acc[tm][tn][1];
            fs[nl * 129 + ml + 8]       = acc[tm][tn][2];
            fs[(nl + 1) * 129 + ml + 8] = acc[tm][tn][3];
        }
    }
    __syncthreads();
    #pragma unroll
    for (int q = 0; q < 16; q++) {
        int pos = q * 256 + tid;
        int r = pos >> 5, c4 = pos & 31;
        int gn = n0 + r, gm = m0 + c4 * 4;
        if (gn < AREA && gm < AREA) {
            float4 v = make_float4(fs[r * 129 + c4 * 4 + 0], fs[r * 129 + c4 * 4 + 1],
                                   fs[r * 129 + c4 * 4 + 2], fs[r * 129 + c4 * 4 + 3]);
            *(float4*)&Dp[(size_t)gn * AREA + gm] = v;
        }
    }
}

// ---------------- scores: diagonal-chained + horizontal (xj) pooling fused ----------------
#define SD_CH 16
#define SD_RS 68
#define SD_SLAB (66 * SD_RS)
#define SD_POOL (64 * 65)
#define SD_SMEM ((4 * SD_SLAB + SD_POOL) * 4)
__global__ __launch_bounds__(256, 2) void k_scores() {
    extern __shared__ float dsm[];
    float* pool = dsm + 4 * SD_SLAB;
    int d = (int)blockIdx.x - 63;
    int chunk = blockIdx.y;
    int b = blockIdx.z;
    int lo = d > 0 ? d : 0;
    int hi = d > 0 ? 63 : 63 + d;
    int xi0 = lo + chunk * SD_CH;
    if (xi0 > hi) return;
    int steps = hi - xi0 + 1; if (steps > SD_CH) steps = SD_CH;
    int tid = threadIdx.x;
    const float* __restrict__ Db = g_D + (size_t)b * AREA * AREA;
    uint32_t sbase = smem_u32(dsm);

    auto load_slab = [&](int u) {
        uint32_t dst = sbase + (uint32_t)(u & 3) * SD_SLAB * 4;
        int col = (u - d) * HP - (((u - d) & 1) ? 2 : 0);
        const float* src = Db + (size_t)(u * HP) * AREA + col;
        #pragma unroll
        for (int q = 0; q < 5; q++) {
            int e = q * 256 + tid;
            if (e < 66 * 17) {
                int r = e / 17, c16 = e - r * 17;
                CP_A16(dst + (r * SD_RS + c16 * 4) * 4, src + (size_t)r * AREA + c16 * 4);
            }
        }
        CP_COMMIT();
    };

    load_slab(xi0); load_slab(xi0 + 1); load_slab(xi0 + 2);

    int lj = tid & 63, xb = tid >> 6;

    #pragma unroll 1
    for (int i = 0; i < steps; i++) {
        int xi = xi0 + i;
        int li = xi - d;
        if (i + 1 < steps) { load_slab(xi + 3); CP_WAIT(1); }
        else CP_WAIT(0);
        __syncthreads();
        int sh0 = (li & 1) ? 2 : 0;
        int sh1 = 2 - sh0;
        const float* s0 = dsm + (size_t)((xi + 0) & 3) * SD_SLAB + sh0;
        const float* s1 = dsm + (size_t)((xi + 1) & 3) * SD_SLAB + sh1;
        const float* s2 = dsm + (size_t)((xi + 2) & 3) * SD_SLAB + sh0;
        #pragma unroll
        for (int q = 0; q < 16; q++) {
            int xj = xb + (q << 2);
            float s = 0.f;
            #pragma unroll
            for (int dx = 0; dx < 3; dx++) {
                int ro = (xj + dx) * SD_RS + lj + dx;
                s += s0[ro] + s1[ro] + s2[ro];
            }
            pool[xj * 65 + lj] = s;
        }
        __syncthreads();
        float iv = g_nm[b * LL + li * 64 + lj];
        float* So = g_S + (size_t)b * LL * LL + (size_t)(xi * 64) * LL + li * 64 + lj;
        #pragma unroll
        for (int q = 0; q < 16; q++) {
            int xj = xb + (q << 2);
            float p = pool[xj * 65 + lj];
            if (xj > 0)  p += pool[(xj - 1) * 65 + lj];
            if (xj < 63) p += pool[(xj + 1) * 65 + lj];
            So[(size_t)xj * LL] = p * iv;
        }
        __syncthreads();
    }
}

// ---------------- vertical 3-tap pool + scale + row softmax ----------------
#define SM_XB 8
__global__ __launch_bounds__(256) void k_softmax() {
    __shared__ __align__(16) float row[LL];
    __shared__ float red[32];
    int b = blockIdx.y, xg = blockIdx.x;
    size_t base = (size_t)b * LL * LL;
    const float4* __restrict__ S4 = (const float4*)(g_S + base);
    int t = threadIdx.x;

    #pragma unroll 1
    for (int xs = 0; xs < SM_XB; xs++) {
        int x = xg * SM_XB + xs;
        int xi = x >> 6, xj = x & 63;
        float cy = (xi == 0 || xi == 63) ? 2.f : 3.f;
        float cx = (xj == 0 || xj == 63) ? 2.f : 3.f;
        float sc = 90.f / (cy * cx);

        int offs4[3]; int no = 0;
        #pragma unroll
        for (int dy = -1; dy <= 1; dy++) {
            if (xi + dy >= 0 && xi + dy < HH)
                offs4[no++] = (x + dy * 64) * (LL / 4);
        }

        float lmax = -1e30f;
        for (int l4 = t; l4 < LL / 4; l4 += 256) {
            float4 s = make_float4(0.f, 0.f, 0.f, 0.f);
            for (int o = 0; o < no; o++) {
                float4 v = __ldg(&S4[offs4[o] + l4]);
                s.x += v.x; s.y += v.y; s.z += v.z; s.w += v.w;
            }
            s.x *= sc; s.y *= sc; s.z *= sc; s.w *= sc;
            ((float4*)row)[l4] = s;
            lmax = fmaxf(fmaxf(fmaxf(lmax, s.x), fmaxf(s.y, s.z)), s.w);
        }
        #pragma unroll
        for (int o = 16; o; o >>= 1) lmax = fmaxf(lmax, __shfl_xor_sync(0xffffffffu, lmax, o));
        if ((t & 31) == 0) red[t >> 5] = lmax;
        __syncthreads();
        if (t < 32) {
            float v = (t < 8) ? red[t] : -1e30f;
            #pragma unroll
            for (int o = 4; o; o >>= 1) v = fmaxf(v, __shfl_xor_sync(0xffffffffu, v, o));
            if (!t) red[0] = v;
        }
        __syncthreads();
        float m = red[0];
        __syncthreads();
        float lsum = 0.f;
        for (int l4 = t; l4 < LL / 4; l4 += 256) {
            float4 s = ((float4*)row)[l4];
            s.x = __expf(s.x - m); s.y = __expf(s.y - m);
            s.z = __expf(s.z - m); s.w = __expf(s.w - m);
            ((float4*)row)[l4] = s;
            lsum += s.x + s.y + s.z + s.w;
        }
        #pragma unroll
        for (int o = 16; o; o >>= 1) lsum += __shfl_xor_sync(0xffffffffu, lsum, o);
        if ((t & 31) == 0) red[t >> 5] = lsum;
        __syncthreads();
        if (t < 32) {
            float v = (t < 8) ? red[t] : 0.f;
            #pragma unroll
            for (int o = 4; o; o >>= 1) v += __shfl_xor_sync(0xffffffffu, v, o);
            if (!t) red[0] = v;
        }
        __syncthreads();
        float inv = 1.f / red[0];
        float4* A4 = (float4*)(g_A + base + (size_t)x * LL);
        for (int l4 = t; l4 < LL / 4; l4 += 256) {
            float4 s = ((float4*)row)[l4];
            s.x *= inv; s.y *= inv; s.z *= inv; s.w *= inv;
            A4[l4] = s;
        }
        __syncthreads();
    }
}

// ---------------- fused W2: vertical diag into smem, horizontal diag emit bf16 ----------------
#define DV_XB 16
#define DV_STR 1032
#define DV_SMEM (18 * DV_STR * 4)
__global__ __launch_bounds__(256, 2) void k_dvh() {
    extern __shared__ float dvb[];
    int b = blockIdx.y;
    int lq = blockIdx.x & 3;
    int xg = blockIdx.x >> 2;
    int x0 = xg * DV_XB;
    int L0 = lq * 1024;
    int t = threadIdx.x;
    int lt = t * 4;
    int l = L0 + lt;
    int li = l >> 6;
    const float* __restrict__ att = g_A + (size_t)b * LL * LL;

    #pragma unroll 1
    for (int j = 0; j < DV_XB + 2; j++) {
        int y = x0 - 1 + j;
        if (y >= 0 && y < LL) {
            int h = y >> 6;
            float4 s = make_float4(0.f, 0.f, 0.f, 0.f);
            #pragma unroll
            for (int sy = -1; sy <= 1; sy++) {
                if ((unsigned)(h + sy) >= 64u || (unsigned)(li + sy) >= 64u) continue;
                float4 v = *(const float4*)(att + (size_t)(y + sy * 64) * LL + l + sy * 64);
                s.x += v.x; s.y += v.y; s.z += v.z; s.w += v.w;
            }
            *(float4*)(dvb + j * DV_STR + lt) = s;
        }
    }
    __syncthreads();

    int lj0 = l & 63;
    #pragma unroll 1
    for (int xs = 0; xs < DV_XB; xs++) {
        int x = x0 + xs;
        int w = x & 63;
        float s[4] = {0.f, 0.f, 0.f, 0.f};
        #pragma unroll
        for (int sx = -1; sx <= 1; sx++) {
            if ((unsigned)(w + sx) >= 64u) continue;
            const float* p = dvb + (xs + 1 + sx) * DV_STR + lt + sx;
            #pragma unroll
            for (int j = 0; j < 4; j++) {
                if ((unsigned)(lj0 + j + sx) < 64u)
                    s[j] += p[j];
            }
        }
        size_t dst = (size_t)b * LL * LL + (size_t)x * LL + l;
        float r0 = s[0] - __bfloat162float(__float2bfloat16(s[0]));
        float r1 = s[1] - __bfloat162float(__float2bfloat16(s[1]));
        float r2 = s[2] - __bfloat162float(__float2bfloat16(s[2]));
        float r3 = s[3] - __bfloat162float(__float2bfloat16(s[3]));
        __nv_bfloat162 h01(__float2bfloat16(s[0]), __float2bfloat16(s[1]));
        __nv_bfloat162 h23(__float2bfloat16(s[2]), __float2bfloat16(s[3]));
        __nv_bfloat162 l01(__float2bfloat16(r0), __float2bfloat16(r1));
        __nv_bfloat162 l23(__float2bfloat16(r2), __float2bfloat16(r3));
        *(__nv_bfloat162*)(g_W2h + dst)     = h01;
        *(__nv_bfloat162*)(g_W2h + dst + 2) = h23;
        *(__nv_bfloat162*)(g_W2l + dst)     = l01;
        *(__nv_bfloat162*)(g_W2l + dst + 2) = l23;
    }
}

// ---------------- y = W2 @ x1 via mma.sync bf16x3, BK=32, 2 CTAs/SM ----------------
#define GA_STR 40      // 32 + 8 pad (conflict-free ldmatrix)
#define GB_STR 136
#define G3_AH  0
#define G3_AL  (128 * GA_STR * 2)                          // 10240 B
#define G3_BH  (2 * 128 * GA_STR * 2)                      // 20480 B
#define G3_BL  (2 * 128 * GA_STR * 2 + 32 * GB_STR * 2)    // 29184 B
#define G3_STG (2 * 128 * GA_STR * 2 + 2 * 32 * GB_STR * 2)  // 37888 B
#define G3_SMEM (2 * G3_STG)                               // 75776 B

__global__ __launch_bounds__(256, 2) void k_gemm3_mma(float* __restrict__ out) {
    extern __shared__ __nv_bfloat16 sm[];
    int tid = threadIdx.x, lane = tid & 31, wid = tid >> 5;
    int wm = wid >> 2, wn = wid & 3;
    int m0 = blockIdx.x * 128;
    int kbeg = blockIdx.y * (LL / 2);
    int b = blockIdx.z;

    const __nv_bfloat16* __restrict__ Ah = g_W2h + (size_t)b * LL * LL;
    const __nv_bfloat16* __restrict__ Al = g_W2l + (size_t)b * LL * LL;
    const __nv_bfloat16* __restrict__ Bh = g_V1h + (size_t)b * LL * CC;
    const __nv_bfloat16* __restrict__ Bl = g_V1l + (size_t)b * LL * CC;

    uint32_t sb = smem_u32(sm);
    float acc[4][4][4];
    #pragma unroll
    for (int i = 0; i < 4; i++)
        #pragma unroll
        for (int j = 0; j < 4; j++)
            #pragma unroll
            for (int q = 0; q < 4; q++) acc[i][j][q] = 0.f;

    int frow = (lane & 7) + ((lane >> 3) & 1) * 8;
    int fcol = ((lane >> 4) & 1) * 8;

    auto load_stage = [&](int s, int k0) {
        uint32_t st = sb + (uint32_t)s * G3_STG;
        // A tiles: 128 rows x 32 bf16 (4 x 16B per row); 512 chunks per plane
        #pragma unroll
        for (int q = 0; q < 2; q++) {
            int e = q * 256 + tid;
            int r = e >> 2, c = e & 3;
            const size_t so = (size_t)(m0 + r) * LL + k0 + c * 8;
            uint32_t doff = (r * GA_STR + c * 8) * 2;
            CP_A16(st + G3_AH + doff, Ah + so);
            CP_A16(st + G3_AL + doff, Al + so);
        }
        // B tiles: 32 rows x 128 bf16 (16 x 16B per row); 512 chunks per plane
        #pragma unroll
        for (int q = 0; q < 2; q++) {
            int e = q * 256 + tid;
            int r = e >> 4, c = e & 15;
            const size_t so = (size_t)(k0 + r) * CC + c * 8;
            uint32_t doff = (r * GB_STR + c * 8) * 2;
            CP_A16(st + G3_BH + doff, Bh + so);
            CP_A16(st + G3_BL + doff, Bl + so);
        }
    };

    load_stage(0, kbeg);
    CP_COMMIT();

    #pragma unroll 1
    for (int ci = 0; ci < 64; ci++) {
        if (ci < 63) { load_stage((ci + 1) & 1, kbeg + (ci + 1) * 32); CP_COMMIT(); }
        if (ci < 63) CP_WAIT(1); else CP_WAIT(0);
        __syncthreads();
        uint32_t st = sb + (uint32_t)(ci & 1) * G3_STG;

        #pragma unroll
        for (int ks = 0; ks < 2; ks++) {
            uint32_t ah[4][4], al[4][4], bh[2][4], bl[2][4];
            #pragma unroll
            for (int tm = 0; tm < 4; tm++) {
                uint32_t off = ((wm * 64 + tm * 16 + frow) * GA_STR + ks * 16 + fcol) * 2;
                LDM_X4(ah[tm][0], ah[tm][1], ah[tm][2], ah[tm][3], st + G3_AH + off);
                LDM_X4(al[tm][0], al[tm][1], al[tm][2], al[tm][3], st + G3_AL + off);
            }
            #pragma unroll
            for (int p = 0; p < 2; p++) {
                uint32_t off = ((ks * 16 + frow) * GB_STR + wn * 32 + p * 16 + fcol) * 2;
                LDM_X4T(bh[p][0], bh[p][1], bh[p][2], bh[p][3], st + G3_BH + off);
                LDM_X4T(bl[p][0], bl[p][1], bl[p][2], bl[p][3], st + G3_BL + off);
            }
            #pragma unroll
            for (int tm = 0; tm < 4; tm++) {
                #pragma unroll
                for (int tn = 0; tn < 4; tn++) {
                    int p = tn >> 1, h2 = (tn & 1) * 2;
                    MMA16816(acc[tm][tn], ah[tm], bh[p][h2], bh[p][h2 + 1]);
                    MMA16816(acc[tm][tn], ah[tm], bl[p][h2], bl[p][h2 + 1]);
                    MMA16816(acc[tm][tn], al[tm], bh[p][h2], bh[p][h2 + 1]);
                }
            }
        }
        __syncthreads();
    }

    float* ob = out + (size_t)b * LL * CC;
    #pragma unroll
    for (int tm = 0; tm < 4; tm++) {
        int row = m0 + wm * 64 + tm * 16 + (lane >> 2);
        #pragma unroll
        for (int tn = 0; tn < 4; tn++) {
            int col = wn * 32 + tn * 8 + (lane & 3) * 2;
            atomicAdd(&ob[(size_t)row * CC + col],           acc[tm][tn][0]);
            atomicAdd(&ob[(size_t)row * CC + col + 1],       acc[tm][tn][1]);
            atomicAdd(&ob[(size_t)(row + 8) * CC + col],     acc[tm][tn][2]);
            atomicAdd(&ob[(size_t)(row + 8) * CC + col + 1], acc[tm][tn][3]);
        }
    }
}

// ---------------- launcher ----------------
extern "C" void kernel_launch(void* const* d_in, const int* in_sizes, int n_in,
                              void* d_out, int out_size) {
    const float* x1 = (const float*)d_in[0];
    const float* x2 = (const float*)d_in[1];
    float* out = (float*)d_out;

    cudaFuncSetAttribute(k_gemm3_mma, cudaFuncAttributeMaxDynamicSharedMemorySize, G3_SMEM);
    cudaFuncSetAttribute(k_scores, cudaFuncAttributeMaxDynamicSharedMemorySize, SD_SMEM);
    cudaFuncSetAttribute(k_dgemm, cudaFuncAttributeMaxDynamicSharedMemorySize, DT_SMEM);
    cudaFuncSetAttribute(k_dvh, cudaFuncAttributeMaxDynamicSharedMemorySize, DV_SMEM);

    dim3 gx((AREA + 31) / 32, CC / 32, BN_);
    k_xt2  <<<gx, dim3(32, 8)>>>(x2);
    k_split<<<(BN_ * LL * CC + 255) / 256, 256>>>(x1, out);
    k_rnorm<<<(BN_ * AREA * 32 + 255) / 256, 256>>>(x2);
    k_nm   <<<(BN_ * LL + 255) / 256, 256>>>();

    dim3 gd(NBLK * (NBLK + 1) / 2, 1, BN_);
    k_dgemm<<<gd, 256, DT_SMEM>>>();

    dim3 gsc(127, 4, BN_);
    k_scores<<<gsc, 256, SD_SMEM>>>();

    dim3 gsm(LL / SM_XB, BN_);
    k_softmax<<<gsm, 256>>>();

    dim3 gdv((LL / DV_XB) * 4, BN_);
    k_dvh<<<gdv, 256, DV_SMEM>>>();

    dim3 gg(LL / 128, 2, BN_);
    k_gemm3_mma<<<gg, 256, G3_SMEM>>>(out);
}

// round 17
// speedup vs baseline: 1.0192x; 1.0192x over previous
#include <cuda_runtime.h>
#include <cuda_bf16.h>
#include <cstdint>

#define BN_  2
#define HH   64
#define WW   64
#define CC   128
#define HP   66
#define AREA 4356          // HP*HP
#define AREAP 4368         // padded stride (16B-aligned in bf16)
#define LL   4096          // HH*WW
#define NBLK 35            // ceil(AREA/128)

// ---------------- scratch ----------------
__device__ __nv_bfloat16 g_X2h[BN_ * AREA * CC + 128 * CC];   // x2 padded hi [b][a][c]
__device__ __nv_bfloat16 g_X2l[BN_ * AREA * CC + 128 * CC];   // x2 padded lo
__device__ __nv_bfloat16 g_XT2h[BN_ * CC * AREAP + 256];      // x2 padded hi, transposed, stride AREAP
__device__ __nv_bfloat16 g_XT2l[BN_ * CC * AREAP + 256];
__device__ float g_r  [BN_ * AREA];
__device__ float g_nm [BN_ * LL];
__device__ float g_D  [(size_t)BN_ * AREA * AREA + 128];
__device__ float g_S  [(size_t)BN_ * LL * LL];        // Sh (pooled-horizontal scores)
__device__ float g_A  [(size_t)BN_ * LL * LL];        // att
__device__ __nv_bfloat16 g_W2h[(size_t)BN_ * LL * LL];
__device__ __nv_bfloat16 g_W2l[(size_t)BN_ * LL * LL];
__device__ __nv_bfloat16 g_V1h[BN_ * LL * CC];
__device__ __nv_bfloat16 g_V1l[BN_ * LL * CC];

// ================= portable PTX helpers =================
__device__ __forceinline__ uint32_t smem_u32(const void* p) {
    uint32_t a;
    asm("{ .reg .u64 t; cvta.to.shared.u64 t, %1; cvt.u32.u64 %0, t; }" : "=r"(a) : "l"(p));
    return a;
}
#define CP_A16(dst, src) asm volatile("cp.async.cg.shared.global [%0], [%1], 16;" :: "r"(dst), "l"(src))
#define CP_COMMIT()      asm volatile("cp.async.commit_group;" ::: "memory")
#define CP_WAIT(n)       asm volatile("cp.async.wait_group %0;" :: "n"(n) : "memory")

#define LDM_X4(r0, r1, r2, r3, addr) \
    asm volatile("ldmatrix.sync.aligned.m8n8.x4.shared.b16 {%0,%1,%2,%3}, [%4];" \
        : "=r"(r0), "=r"(r1), "=r"(r2), "=r"(r3) : "r"(addr))
#define LDM_X4T(r0, r1, r2, r3, addr) \
    asm volatile("ldmatrix.sync.aligned.m8n8.x4.trans.shared.b16 {%0,%1,%2,%3}, [%4];" \
        : "=r"(r0), "=r"(r1), "=r"(r2), "=r"(r3) : "r"(addr))
#define MMA16816(d, a, b0v, b1v) \
    asm volatile("mma.sync.aligned.m16n8k16.row.col.f32.bf16.bf16.f32 " \
        "{%0,%1,%2,%3}, {%4,%5,%6,%7}, {%8,%9}, {%0,%1,%2,%3};" \
        : "+f"((d)[0]), "+f"((d)[1]), "+f"((d)[2]), "+f"((d)[3]) \
        : "r"((a)[0]), "r"((a)[1]), "r"((a)[2]), "r"((a)[3]), "r"(b0v), "r"(b1v))

// ---------------- transpose x2 → bf16 hi/lo both layouts (one x2 pass) ----------------
__global__ void k_xt2(const float* __restrict__ x2) {
    __shared__ float t[32][33];
    int b = blockIdx.z;
    int a0 = blockIdx.x * 32, c0 = blockIdx.y * 32;
    int tx = threadIdx.x, ty = threadIdx.y;
    #pragma unroll
    for (int i = 0; i < 4; i++) {
        int r = ty + i * 8;
        int a = a0 + r;
        if (a < AREA) {
            int ai = a / HP, aj = a % HP;
            float v = 0.f;
            if (ai >= 1 && ai <= HH && aj >= 1 && aj <= WW)
                v = x2[((size_t)(b * HH + ai - 1) * WW + aj - 1) * CC + c0 + tx];
            t[r][tx] = v;
            __nv_bfloat16 h = __float2bfloat16(v);
            size_t dst = ((size_t)(b * AREA + a)) * CC + c0 + tx;
            g_X2h[dst] = h;
            g_X2l[dst] = __float2bfloat16(v - __bfloat162float(h));
        }
    }
    __syncthreads();
    #pragma unroll
    for (int i = 0; i < 4; i++) {
        int r = ty + i * 8;
        if (a0 + tx < AREA) {
            float v = t[tx][r];
            __nv_bfloat16 h = __float2bfloat16(v);
            size_t dst = ((size_t)b * CC + c0 + r) * AREAP + a0 + tx;
            g_XT2h[dst] = h;
            g_XT2l[dst] = __float2bfloat16(v - __bfloat162float(h));
        }
    }
}

// ---------------- split x1 into bf16 hi/lo + zero output ----------------
__global__ void k_split(const float* __restrict__ x1, float* __restrict__ out) {
    int idx = blockIdx.x * blockDim.x + threadIdx.x;
    if (idx >= BN_ * LL * CC) return;
    float v = x1[idx];
    __nv_bfloat16 h = __float2bfloat16(v);
    g_V1h[idx] = h;
    g_V1l[idx] = __float2bfloat16(v - __bfloat162float(h));
    out[idx] = 0.f;
}

// ---------------- per-pixel squared norms ----------------
__global__ void k_rnorm(const float* __restrict__ x2) {
    int gw = (blockIdx.x * blockDim.x + threadIdx.x) >> 5;
    int lane = threadIdx.x & 31;
    if (gw >= BN_ * AREA) return;
    int a = gw % AREA, b = gw / AREA;
    int ai = a / HP, aj = a % HP;
    float s = 0.f;
    if (ai >= 1 && ai <= HH && aj >= 1 && aj <= WW) {
        const float4* p = (const float4*)(x2 + ((size_t)(b * HH + ai - 1) * WW + aj - 1) * CC);
        float4 v = p[lane];
        s = v.x * v.x + v.y * v.y + v.z * v.z + v.w * v.w;
        #pragma unroll
        for (int o = 16; o; o >>= 1) s += __shfl_xor_sync(0xffffffffu, s, o);
    }
    if (!lane) g_r[gw] = s;
}

// ---------------- patch norms ----------------
__global__ void k_nm() {
    int idx = blockIdx.x * blockDim.x + threadIdx.x;
    if (idx >= BN_ * LL) return;
    int l = idx & (LL - 1), b = idx / LL;
    int li = l >> 6, lj = l & 63;
    const float* rb = g_r + b * AREA;
    float s = 0.f;
    #pragma unroll
    for (int dy = 0; dy < 3; dy++)
        #pragma unroll
        for (int dx = 0; dx < 3; dx++)
            s += rb[(li + dy) * HP + lj + dx];
    g_nm[idx] = 1.f / fmaxf(sqrtf(s), 1e-4f);
}

// ---------------- D = X @ X^T via mma.sync bf16x3, symmetric blocks ----------------
#define DT_STR 136
#define DT_TILE (128 * DT_STR)
#define DT_SMEM (4 * DT_TILE * 2)       // 139264 B
__global__ __launch_bounds__(256, 1) void k_dgemm() {
    extern __shared__ __nv_bfloat16 sm[];
    int rem = blockIdx.x;
    int bm = 0;
    while (rem >= NBLK - bm) { rem -= NBLK - bm; bm++; }
    int bn = bm + rem;
    int b = blockIdx.z;
    int m0 = bm * 128, n0 = bn * 128;
    int tid = threadIdx.x, lane = tid & 31, wid = tid >> 5;
    int wm = wid >> 2, wn = wid & 3;

    const __nv_bfloat16* __restrict__ Axh = g_X2h + (size_t)b * AREA * CC;
    const __nv_bfloat16* __restrict__ Axl = g_X2l + (size_t)b * AREA * CC;
    const __nv_bfloat16* __restrict__ Bxh = g_XT2h + (size_t)b * CC * AREAP;
    const __nv_bfloat16* __restrict__ Bxl = g_XT2l + (size_t)b * CC * AREAP;
    float* __restrict__ Dp = g_D + (size_t)b * AREA * AREA;
    uint32_t sb = smem_u32(sm);

    #pragma unroll
    for (int q = 0; q < 8; q++) {
        int e = q * 256 + tid;
        int r = e >> 4, c = e & 15;
        uint32_t doff = (r * DT_STR + c * 8) * 2;
        size_t soA = (size_t)(m0 + r) * CC + c * 8;
        CP_A16(sb + 0 * DT_TILE * 2 + doff, Axh + soA);
        CP_A16(sb + 1 * DT_TILE * 2 + doff, Axl + soA);
        size_t soB = (size_t)r * AREAP + n0 + c * 8;
        CP_A16(sb + 2 * DT_TILE * 2 + doff, Bxh + soB);
        CP_A16(sb + 3 * DT_TILE * 2 + doff, Bxl + soB);
    }
    CP_COMMIT();
    CP_WAIT(0);
    __syncthreads();

    float acc[4][4][4];
    #pragma unroll
    for (int i = 0; i < 4; i++)
        #pragma unroll
        for (int j = 0; j < 4; j++)
            #pragma unroll
            for (int q = 0; q < 4; q++) acc[i][j][q] = 0.f;

    int frow = (lane & 7) + ((lane >> 3) & 1) * 8;
    int fcol = ((lane >> 4) & 1) * 8;

    #pragma unroll
    for (int ks = 0; ks < 8; ks++) {
        uint32_t ah[4][4], al[4][4], bh[2][4], bl[2][4];
        #pragma unroll
        for (int tm = 0; tm < 4; tm++) {
            uint32_t off = ((wm * 64 + tm * 16 + frow) * DT_STR + ks * 16 + fcol) * 2;
            LDM_X4(ah[tm][0], ah[tm][1], ah[tm][2], ah[tm][3], sb + 0 * DT_TILE * 2 + off);
            LDM_X4(al[tm][0], al[tm][1], al[tm][2], al[tm][3], sb + 1 * DT_TILE * 2 + off);
        }
        #pragma unroll
        for (int p = 0; p < 2; p++) {
            uint32_t off = ((ks * 16 + frow) * DT_STR + wn * 32 + p * 16 + fcol) * 2;
            LDM_X4T(bh[p][0], bh[p][1], bh[p][2], bh[p][3], sb + 2 * DT_TILE * 2 + off);
            LDM_X4T(bl[p][0], bl[p][1], bl[p][2], bl[p][3], sb + 3 * DT_TILE * 2 + off);
        }
        #pragma unroll
        for (int tm = 0; tm < 4; tm++) {
            #pragma unroll
            for (int tn = 0; tn < 4; tn++) {
                int p = tn >> 1, h2 = (tn & 1) * 2;
                MMA16816(acc[tm][tn], ah[tm], bh[p][h2], bh[p][h2 + 1]);
                MMA16816(acc[tm][tn], ah[tm], bl[p][h2], bl[p][h2 + 1]);
                MMA16816(acc[tm][tn], al[tm], bh[p][h2], bh[p][h2 + 1]);
            }
        }
    }

    // normal store (rows m, evict-first: D is single-use streaming data)
    #pragma unroll
    for (int tm = 0; tm < 4; tm++) {
        int row = m0 + wm * 64 + tm * 16 + (lane >> 2);
        #pragma unroll
        for (int tn = 0; tn < 4; tn++) {
            int col = n0 + wn * 32 + tn * 8 + (lane & 3) * 2;
            if (col < AREA) {
                if (row < AREA)
                    __stcs((float2*)&Dp[(size_t)row * AREA + col], make_float2(acc[tm][tn][0], acc[tm][tn][1]));
                if (row + 8 < AREA)
                    __stcs((float2*)&Dp[(size_t)(row + 8) * AREA + col], make_float2(acc[tm][tn][2], acc[tm][tn][3]));
            }
        }
    }

    if (bm == bn) return;

    __syncthreads();
    float* fs = (float*)sm;
    #pragma unroll
    for (int tm = 0; tm < 4; tm++) {
        int ml = wm * 64 + tm * 16 + (lane >> 2);
        #pragma unroll
        for (int tn = 0; tn < 4; tn++) {
            int nl = wn * 32 + tn * 8 + (lane & 3) * 2;
            fs[nl * 129 + ml]           = acc[tm][tn][0];
            fs[(nl + 1) * 129 + ml]     = acc[tm][tn][1];
            fs[nl * 129 + ml + 8]       = acc[tm][tn][2];
            fs[(nl + 1) * 129 + ml + 8] = acc[tm][tn][3];
        }
    }
    __syncthreads();
    #pragma unroll
    for (int q = 0; q < 16; q++) {
        int pos = q * 256 + tid;
        int r = pos >> 5, c4 = pos & 31;
        int gn = n0 + r, gm = m0 + c4 * 4;
        if (gn < AREA && gm < AREA) {
            float4 v = make_float4(fs[r * 129 + c4 * 4 + 0], fs[r * 129 + c4 * 4 + 1],
                                   fs[r * 129 + c4 * 4 + 2], fs[r * 129 + c4 * 4 + 3]);
            __stcs((float4*)&Dp[(size_t)gn * AREA + gm], v);
        }
    }
}

// ---------------- scores: diagonal-chained + horizontal (xj) pooling fused ----------------
#define SD_CH 16
#define SD_RS 68
#define SD_SLAB (66 * SD_RS)
#define SD_POOL (64 * 65)
#define SD_SMEM ((4 * SD_SLAB + SD_POOL) * 4)
__global__ __launch_bounds__(256, 2) void k_scores() {
    extern __shared__ float dsm[];
    float* pool = dsm + 4 * SD_SLAB;
    int d = (int)blockIdx.x - 63;
    int chunk = blockIdx.y;
    int b = blockIdx.z;
    int lo = d > 0 ? d : 0;
    int hi = d > 0 ? 63 : 63 + d;
    int xi0 = lo + chunk * SD_CH;
    if (xi0 > hi) return;
    int steps = hi - xi0 + 1; if (steps > SD_CH) steps = SD_CH;
    int tid = threadIdx.x;
    const float* __restrict__ Db = g_D + (size_t)b * AREA * AREA;
    uint32_t sbase = smem_u32(dsm);

    auto load_slab = [&](int u) {
        uint32_t dst = sbase + (uint32_t)(u & 3) * SD_SLAB * 4;
        int col = (u - d) * HP - (((u - d) & 1) ? 2 : 0);
        const float* src = Db + (size_t)(u * HP) * AREA + col;
        #pragma unroll
        for (int q = 0; q < 5; q++) {
            int e = q * 256 + tid;
            if (e < 66 * 17) {
                int r = e / 17, c16 = e - r * 17;
                CP_A16(dst + (r * SD_RS + c16 * 4) * 4, src + (size_t)r * AREA + c16 * 4);
            }
        }
        CP_COMMIT();
    };

    load_slab(xi0); load_slab(xi0 + 1); load_slab(xi0 + 2);

    int lj = tid & 63, xb = tid >> 6;

    #pragma unroll 1
    for (int i = 0; i < steps; i++) {
        int xi = xi0 + i;
        int li = xi - d;
        if (i + 1 < steps) { load_slab(xi + 3); CP_WAIT(1); }
        else CP_WAIT(0);
        __syncthreads();
        int sh0 = (li & 1) ? 2 : 0;
        int sh1 = 2 - sh0;
        const float* s0 = dsm + (size_t)((xi + 0) & 3) * SD_SLAB + sh0;
        const float* s1 = dsm + (size_t)((xi + 1) & 3) * SD_SLAB + sh1;
        const float* s2 = dsm + (size_t)((xi + 2) & 3) * SD_SLAB + sh0;
        #pragma unroll
        for (int q = 0; q < 16; q++) {
            int xj = xb + (q << 2);
            float s = 0.f;
            #pragma unroll
            for (int dx = 0; dx < 3; dx++) {
                int ro = (xj + dx) * SD_RS + lj + dx;
                s += s0[ro] + s1[ro] + s2[ro];
            }
            pool[xj * 65 + lj] = s;
        }
        __syncthreads();
        float iv = g_nm[b * LL + li * 64 + lj];
        float* So = g_S + (size_t)b * LL * LL + (size_t)(xi * 64) * LL + li * 64 + lj;
        #pragma unroll
        for (int q = 0; q < 16; q++) {
            int xj = xb + (q << 2);
            float p = pool[xj * 65 + lj];
            if (xj > 0)  p += pool[(xj - 1) * 65 + lj];
            if (xj < 63) p += pool[(xj + 1) * 65 + lj];
            So[(size_t)xj * LL] = p * iv;
        }
        __syncthreads();
    }
}

// ---------------- vertical 3-tap pool + scale + row softmax ----------------
#define SM_XB 8
__global__ __launch_bounds__(256) void k_softmax() {
    __shared__ __align__(16) float row[LL];
    __shared__ float red[32];
    int b = blockIdx.y, xg = blockIdx.x;
    size_t base = (size_t)b * LL * LL;
    const float4* __restrict__ S4 = (const float4*)(g_S + base);
    int t = threadIdx.x;

    #pragma unroll 1
    for (int xs = 0; xs < SM_XB; xs++) {
        int x = xg * SM_XB + xs;
        int xi = x >> 6, xj = x & 63;
        float cy = (xi == 0 || xi == 63) ? 2.f : 3.f;
        float cx = (xj == 0 || xj == 63) ? 2.f : 3.f;
        float sc = 90.f / (cy * cx);

        int offs4[3]; int no = 0;
        #pragma unroll
        for (int dy = -1; dy <= 1; dy++) {
            if (xi + dy >= 0 && xi + dy < HH)
                offs4[no++] = (x + dy * 64) * (LL / 4);
        }

        float lmax = -1e30f;
        for (int l4 = t; l4 < LL / 4; l4 += 256) {
            float4 s = make_float4(0.f, 0.f, 0.f, 0.f);
            for (int o = 0; o < no; o++) {
                float4 v = __ldg(&S4[offs4[o] + l4]);
                s.x += v.x; s.y += v.y; s.z += v.z; s.w += v.w;
            }
            s.x *= sc; s.y *= sc; s.z *= sc; s.w *= sc;
            ((float4*)row)[l4] = s;
            lmax = fmaxf(fmaxf(fmaxf(lmax, s.x), fmaxf(s.y, s.z)), s.w);
        }
        #pragma unroll
        for (int o = 16; o; o >>= 1) lmax = fmaxf(lmax, __shfl_xor_sync(0xffffffffu, lmax, o));
        if ((t & 31) == 0) red[t >> 5] = lmax;
        __syncthreads();
        if (t < 32) {
            float v = (t < 8) ? red[t] : -1e30f;
            #pragma unroll
            for (int o = 4; o; o >>= 1) v = fmaxf(v, __shfl_xor_sync(0xffffffffu, v, o));
            if (!t) red[0] = v;
        }
        __syncthreads();
        float m = red[0];
        __syncthreads();
        float lsum = 0.f;
        for (int l4 = t; l4 < LL / 4; l4 += 256) {
            float4 s = ((float4*)row)[l4];
            s.x = __expf(s.x - m); s.y = __expf(s.y - m);
            s.z = __expf(s.z - m); s.w = __expf(s.w - m);
            ((float4*)row)[l4] = s;
            lsum += s.x + s.y + s.z + s.w;
        }
        #pragma unroll
        for (int o = 16; o; o >>= 1) lsum += __shfl_xor_sync(0xffffffffu, lsum, o);
        if ((t & 31) == 0) red[t >> 5] = lsum;
        __syncthreads();
        if (t < 32) {
            float v = (t < 8) ? red[t] : 0.f;
            #pragma unroll
            for (int o = 4; o; o >>= 1) v += __shfl_xor_sync(0xffffffffu, v, o);
            if (!t) red[0] = v;
        }
        __syncthreads();
        float inv = 1.f / red[0];
        float4* A4 = (float4*)(g_A + base + (size_t)x * LL);
        for (int l4 = t; l4 < LL / 4; l4 += 256) {
            float4 s = ((float4*)row)[l4];
            s.x *= inv; s.y *= inv; s.z *= inv; s.w *= inv;
            A4[l4] = s;
        }
        __syncthreads();
    }
}

// ---------------- fused W2: vertical diag into smem, horizontal diag emit bf16 ----------------
#define DV_XB 16
#define DV_STR 1032
#define DV_SMEM (18 * DV_STR * 4)
__global__ __launch_bounds__(256, 2) void k_dvh() {
    extern __shared__ float dvb[];
    int b = blockIdx.y;
    int lq = blockIdx.x & 3;
    int xg = blockIdx.x >> 2;
    int x0 = xg * DV_XB;
    int L0 = lq * 1024;
    int t = threadIdx.x;
    int lt = t * 4;
    int l = L0 + lt;
    int li = l >> 6;
    const float* __restrict__ att = g_A + (size_t)b * LL * LL;

    #pragma unroll 1
    for (int j = 0; j < DV_XB + 2; j++) {
        int y = x0 - 1 + j;
        if (y >= 0 && y < LL) {
            int h = y >> 6;
            float4 s = make_float4(0.f, 0.f, 0.f, 0.f);
            #pragma unroll
            for (int sy = -1; sy <= 1; sy++) {
                if ((unsigned)(h + sy) >= 64u || (unsigned)(li + sy) >= 64u) continue;
                float4 v = *(const float4*)(att + (size_t)(y + sy * 64) * LL + l + sy * 64);
                s.x += v.x; s.y += v.y; s.z += v.z; s.w += v.w;
            }
            *(float4*)(dvb + j * DV_STR + lt) = s;
        }
    }
    __syncthreads();

    int lj0 = l & 63;
    #pragma unroll 1
    for (int xs = 0; xs < DV_XB; xs++) {
        int x = x0 + xs;
        int w = x & 63;
        float s[4] = {0.f, 0.f, 0.f, 0.f};
        #pragma unroll
        for (int sx = -1; sx <= 1; sx++) {
            if ((unsigned)(w + sx) >= 64u) continue;
            const float* p = dvb + (xs + 1 + sx) * DV_STR + lt + sx;
            #pragma unroll
            for (int j = 0; j < 4; j++) {
                if ((unsigned)(lj0 + j + sx) < 64u)
                    s[j] += p[j];
            }
        }
        size_t dst = (size_t)b * LL * LL + (size_t)x * LL + l;
        float r0 = s[0] - __bfloat162float(__float2bfloat16(s[0]));
        float r1 = s[1] - __bfloat162float(__float2bfloat16(s[1]));
        float r2 = s[2] - __bfloat162float(__float2bfloat16(s[2]));
        float r3 = s[3] - __bfloat162float(__float2bfloat16(s[3]));
        __nv_bfloat162 h01(__float2bfloat16(s[0]), __float2bfloat16(s[1]));
        __nv_bfloat162 h23(__float2bfloat16(s[2]), __float2bfloat16(s[3]));
        __nv_bfloat162 l01(__float2bfloat16(r0), __float2bfloat16(r1));
        __nv_bfloat162 l23(__float2bfloat16(r2), __float2bfloat16(r3));
        *(__nv_bfloat162*)(g_W2h + dst)     = h01;
        *(__nv_bfloat162*)(g_W2h + dst + 2) = h23;
        *(__nv_bfloat162*)(g_W2l + dst)     = l01;
        *(__nv_bfloat162*)(g_W2l + dst + 2) = l23;
    }
}

// ---------------- y = W2 @ x1 via mma.sync bf16x3, cp.async double-buffered (BK=64) ----------------
#define GA_STR 72
#define GB_STR 136
#define G3_AH  0
#define G3_AL  (128 * GA_STR * 2)
#define G3_BH  (2 * 128 * GA_STR * 2)
#define G3_BL  (2 * 128 * GA_STR * 2 + 64 * GB_STR * 2)
#define G3_STG (2 * 128 * GA_STR * 2 + 2 * 64 * GB_STR * 2)
#define G3_SMEM (2 * G3_STG)

__global__ __launch_bounds__(256, 1) void k_gemm3_mma(float* __restrict__ out) {
    extern __shared__ __nv_bfloat16 sm[];
    int tid = threadIdx.x, lane = tid & 31, wid = tid >> 5;
    int wm = wid >> 2, wn = wid & 3;
    int m0 = blockIdx.x * 128;
    int kbeg = blockIdx.y * (LL / 2);
    int b = blockIdx.z;

    const __nv_bfloat16* __restrict__ Ah = g_W2h + (size_t)b * LL * LL;
    const __nv_bfloat16* __restrict__ Al = g_W2l + (size_t)b * LL * LL;
    const __nv_bfloat16* __restrict__ Bh = g_V1h + (size_t)b * LL * CC;
    const __nv_bfloat16* __restrict__ Bl = g_V1l + (size_t)b * LL * CC;

    uint32_t sb = smem_u32(sm);
    float acc[4][4][4];
    #pragma unroll
    for (int i = 0; i < 4; i++)
        #pragma unroll
        for (int j = 0; j < 4; j++)
            #pragma unroll
            for (int q = 0; q < 4; q++) acc[i][j][q] = 0.f;

    int frow = (lane & 7) + ((lane >> 3) & 1) * 8;
    int fcol = ((lane >> 4) & 1) * 8;

    auto load_stage = [&](int s, int k0) {
        uint32_t st = sb + (uint32_t)s * G3_STG;
        #pragma unroll
        for (int q = 0; q < 4; q++) {
            int e = q * 256 + tid;
            int r = e >> 3, c = e & 7;
            const size_t so = (size_t)(m0 + r) * LL + k0 + c * 8;
            uint32_t doff = (r * GA_STR + c * 8) * 2;
            CP_A16(st + G3_AH + doff, Ah + so);
            CP_A16(st + G3_AL + doff, Al + so);
        }
        #pragma unroll
        for (int q = 0; q < 4; q++) {
            int e = q * 256 + tid;
            int r = e >> 4, c = e & 15;
            const size_t so = (size_t)(k0 + r) * CC + c * 8;
            uint32_t doff = (r * GB_STR + c * 8) * 2;
            CP_A16(st + G3_BH + doff, Bh + so);
            CP_A16(st + G3_BL + doff, Bl + so);
        }
    };

    load_stage(0, kbeg);
    CP_COMMIT();

    #pragma unroll 1
    for (int ci = 0; ci < 32; ci++) {
        if (ci < 31) { load_stage((ci + 1) & 1, kbeg + (ci + 1) * 64); CP_COMMIT(); }
        if (ci < 31) CP_WAIT(1); else CP_WAIT(0);
        __syncthreads();
        uint32_t st = sb + (uint32_t)(ci & 1) * G3_STG;

        #pragma unroll
        for (int ks = 0; ks < 4; ks++) {
            uint32_t ah[4][4], al[4][4], bh[2][4], bl[2][4];
            #pragma unroll
            for (int tm = 0; tm < 4; tm++) {
                uint32_t off = ((wm * 64 + tm * 16 + frow) * GA_STR + ks * 16 + fcol) * 2;
                LDM_X4(ah[tm][0], ah[tm][1], ah[tm][2], ah[tm][3], st + G3_AH + off);
                LDM_X4(al[tm][0], al[tm][1], al[tm][2], al[tm][3], st + G3_AL + off);
            }
            #pragma unroll
            for (int p = 0; p < 2; p++) {
                uint32_t off = ((ks * 16 + frow) * GB_STR + wn * 32 + p * 16 + fcol) * 2;
                LDM_X4T(bh[p][0], bh[p][1], bh[p][2], bh[p][3], st + G3_BH + off);
                LDM_X4T(bl[p][0], bl[p][1], bl[p][2], bl[p][3], st + G3_BL + off);
            }
            #pragma unroll
            for (int tm = 0; tm < 4; tm++) {
                #pragma unroll
                for (int tn = 0; tn < 4; tn++) {
                    int p = tn >> 1, h2 = (tn & 1) * 2;
                    MMA16816(acc[tm][tn], ah[tm], bh[p][h2], bh[p][h2 + 1]);
                    MMA16816(acc[tm][tn], ah[tm], bl[p][h2], bl[p][h2 + 1]);
                    MMA16816(acc[tm][tn], al[tm], bh[p][h2], bh[p][h2 + 1]);
                }
            }
        }
        __syncthreads();
    }

    float* ob = out + (size_t)b * LL * CC;
    #pragma unroll
    for (int tm = 0; tm < 4; tm++) {
        int row = m0 + wm * 64 + tm * 16 + (lane >> 2);
        #pragma unroll
        for (int tn = 0; tn < 4; tn++) {
            int col = wn * 32 + tn * 8 + (lane & 3) * 2;
            atomicAdd(&ob[(size_t)row * CC + col],           acc[tm][tn][0]);
            atomicAdd(&ob[(size_t)row * CC + col + 1],       acc[tm][tn][1]);
            atomicAdd(&ob[(size_t)(row + 8) * CC + col],     acc[tm][tn][2]);
            atomicAdd(&ob[(size_t)(row + 8) * CC + col + 1], acc[tm][tn][3]);
        }
    }
}

// ---------------- launcher ----------------
extern "C" void kernel_launch(void* const* d_in, const int* in_sizes, int n_in,
                              void* d_out, int out_size) {
    const float* x1 = (const float*)d_in[0];
    const float* x2 = (const float*)d_in[1];
    float* out = (float*)d_out;

    cudaFuncSetAttribute(k_gemm3_mma, cudaFuncAttributeMaxDynamicSharedMemorySize, G3_SMEM);
    cudaFuncSetAttribute(k_scores, cudaFuncAttributeMaxDynamicSharedMemorySize, SD_SMEM);
    cudaFuncSetAttribute(k_dgemm, cudaFuncAttributeMaxDynamicSharedMemorySize, DT_SMEM);
    cudaFuncSetAttribute(k_dvh, cudaFuncAttributeMaxDynamicSharedMemorySize, DV_SMEM);

    dim3 gx((AREA + 31) / 32, CC / 32, BN_);
    k_xt2  <<<gx, dim3(32, 8)>>>(x2);
    k_split<<<(BN_ * LL * CC + 255) / 256, 256>>>(x1, out);
    k_rnorm<<<(BN_ * AREA * 32 + 255) / 256, 256>>>(x2);
    k_nm   <<<(BN_ * LL + 255) / 256, 256>>>();

    dim3 gd(NBLK * (NBLK + 1) / 2, 1, BN_);
    k_dgemm<<<gd, 256, DT_SMEM>>>();

    dim3 gsc(127, 4, BN_);
    k_scores<<<gsc, 256, SD_SMEM>>>();

    dim3 gsm(LL / SM_XB, BN_);
    k_softmax<<<gsm, 256>>>();

    dim3 gdv((LL / DV_XB) * 4, BN_);
    k_dvh<<<gdv, 256, DV_SMEM>>>();

    dim3 gg(LL / 128, 2, BN_);
    k_gemm3_mma<<<gg, 256, G3_SMEM>>>(out);
}